// round 1
// baseline (speedup 1.0000x reference)
#include <cuda_runtime.h>
#include <math.h>

// ---------------- problem constants (fixed shapes) ----------------
#define BATCH 8
#define C     64
#define HH    64
#define WW    64
#define HW    4096          // 64*64
#define HEADS 4
#define DK    32
#define HD    128           // HEADS*DK
#define KHW   1024          // 32*32 (stride-2 output)
#define THETA 0.5f
#define EPS_LN 1e-5f
#define NTOT  (BATCH*C*HW)  // 2097152
#define QK_SCALE 0.17677669529663687f  // 1/sqrt(32)

// ---------------- device scratch (static, allowed) ----------------
__device__ double g_sums[2];
__device__ float  g_stats[2];                       // mean, rstd
__device__ float  g_weffk[512*128];                 // [ci*8+t][f]
__device__ float  g_weffv[512*128];
__device__ float  g_q[BATCH*HEADS*HW*DK];           // 16 MB
__device__ float  g_k[BATCH*HEADS*KHW*DK];          // 4 MB
__device__ float  g_v[BATCH*HEADS*KHW*DK];          // 4 MB
__device__ float  g_ctx[BATCH*HW*HD];               // 16 MB

// ---------------- stage 0: global mean/var ----------------
__global__ void k_zero()
{
    g_sums[0] = 0.0; g_sums[1] = 0.0;
}

__global__ void k_reduce(const float* __restrict__ x, int n)
{
    float s = 0.f, s2 = 0.f;
    for (int i = blockIdx.x*blockDim.x + threadIdx.x; i < n; i += gridDim.x*blockDim.x) {
        float v = x[i];
        s  += v;
        s2  = fmaf(v, v, s2);
    }
    #pragma unroll
    for (int off = 16; off; off >>= 1) {
        s  += __shfl_down_sync(0xffffffffu, s,  off);
        s2 += __shfl_down_sync(0xffffffffu, s2, off);
    }
    __shared__ float sh[2][8];
    int lane = threadIdx.x & 31, w = threadIdx.x >> 5;
    if (lane == 0) { sh[0][w] = s; sh[1][w] = s2; }
    __syncthreads();
    if (threadIdx.x == 0) {
        double ds = 0.0, ds2 = 0.0;
        for (int i = 0; i < 8; i++) { ds += (double)sh[0][i]; ds2 += (double)sh[1][i]; }
        atomicAdd(&g_sums[0], ds);
        atomicAdd(&g_sums[1], ds2);
    }
}

__global__ void k_finalize()
{
    double n = (double)NTOT;
    double m = g_sums[0] / n;
    double var = g_sums[1] / n - m*m;
    g_stats[0] = (float)m;
    g_stats[1] = (float)rsqrt(var + (double)EPS_LN);
}

// ---------------- stage 1: fold conv weights into FC: Weff ----------------
// Weff_T[(ci*8+t)*128 + f] = sum_co fc_w[f*64+co] * w8[co*512 + ci*8 + t]
__global__ void k_weff(const float* __restrict__ fck_w, const float* __restrict__ wk,
                       const float* __restrict__ fcv_w, const float* __restrict__ wv)
{
    int t = blockIdx.x*blockDim.x + threadIdx.x;   // 0..65535
    const float* fw = blockIdx.y ? fcv_w : fck_w;
    const float* w8 = blockIdx.y ? wv    : wk;
    float*      out = blockIdx.y ? g_weffv : g_weffk;
    int f = t & 127, idx = t >> 7;
    float acc = 0.f;
    #pragma unroll 8
    for (int co = 0; co < 64; co++)
        acc = fmaf(fw[f*64+co], w8[co*512+idx], acc);
    out[idx*128+f] = acc;
}

// ---------------- stage 2: Q projection (with global LN) ----------------
// grid (HW/16, BATCH), 128 threads. Thread = feature f, 16 positions per block.
__global__ void k_qproj(const float* __restrict__ x,
                        const float* __restrict__ fcq_w,
                        const float* __restrict__ fcq_b)
{
    __shared__ float xs[64*16];     // [c][pos]
    __shared__ float ws[64*129];    // [c][f] padded
    int b   = blockIdx.y;
    int p0  = blockIdx.x * 16;
    int tid = threadIdx.x;
    float mean = g_stats[0], rstd = g_stats[1];

    for (int e = tid; e < 8192; e += 128) {
        int f = e >> 6, c = e & 63;
        ws[c*129+f] = fcq_w[e];
    }
    const float* xb = x + (size_t)b*C*HW;
    for (int e = tid; e < 1024; e += 128) {
        int c = e >> 4, pos = e & 15;
        xs[c*16+pos] = (xb[c*HW + p0 + pos] - mean) * rstd;
    }
    __syncthreads();

    int f = tid;
    float acc[16];
    float bias = fcq_b[f];
    #pragma unroll
    for (int i = 0; i < 16; i++) acc[i] = bias;
    for (int c = 0; c < 64; c++) {
        float wv_ = ws[c*129+f];
        #pragma unroll
        for (int i = 0; i < 16; i++) acc[i] = fmaf(wv_, xs[c*16+i], acc[i]);
    }
    int h = f >> 5, d = f & 31;
    float* qb = g_q + ((size_t)(b*HEADS+h)*HW)*DK + d;
    #pragma unroll
    for (int i = 0; i < 16; i++) qb[(size_t)(p0+i)*DK] = acc[i];
}

// ---------------- stage 3: PDC conv + K/V projection fused ----------------
// grid (KHW/16, BATCH), 128 threads. Thread = feature f, 16 output positions.
__global__ void k_kv(const float* __restrict__ x,
                     const float* __restrict__ fck_b,
                     const float* __restrict__ fcv_b)
{
    __shared__ float gs[16*512];    // 32 KB: [pos][ci*8+t]
    int b   = blockIdx.y;
    int p0  = blockIdx.x * 16;
    int tid = threadIdx.x;
    const float* xb = x + (size_t)b*C*HW;

    for (int e = tid; e < 8192; e += 128) {
        int pos = e >> 9;
        int idx = e & 511;
        int ci = idx >> 3, t = idx & 7;
        int pg = p0 + pos;
        int i = pg >> 5, j = pg & 31;
        int cy = i*2, cx = j*2;
        int k9 = (t < 4) ? t : t + 1;      // skip 3x3 center
        int ny = cy + (k9/3) - 1;
        int nx = cx + (k9%3) - 1;
        float ctr = xb[ci*HW + cy*WW + cx];
        float nb = 0.f;
        if (ny >= 0 && ny < HH && nx >= 0 && nx < WW)
            nb = xb[ci*HW + ny*WW + nx];
        gs[pos*512+idx] = nb - THETA*ctr;
    }
    __syncthreads();

    int f = tid;
    float ak[16], av[16];
    float bk = fck_b[f], bv = fcv_b[f];
    #pragma unroll
    for (int i = 0; i < 16; i++) { ak[i] = bk; av[i] = bv; }
    for (int idx = 0; idx < 512; idx++) {
        float wk_ = g_weffk[idx*128+f];
        float wv_ = g_weffv[idx*128+f];
        #pragma unroll
        for (int i = 0; i < 16; i++) {
            float gg = gs[i*512+idx];
            ak[i] = fmaf(wk_, gg, ak[i]);
            av[i] = fmaf(wv_, gg, av[i]);
        }
    }
    int h = f >> 5, d = f & 31;
    #pragma unroll
    for (int i = 0; i < 16; i++) {
        size_t addr = ((size_t)(b*HEADS+h)*KHW + p0 + i)*DK + d;
        g_k[addr] = ak[i];
        g_v[addr] = av[i];
    }
}

// ---------------- stage 4: attention (max-free online softmax) ----------------
// grid (HW/128, BATCH*HEADS), 128 threads; one query row per thread.
__global__ void k_attn(const float* __restrict__ Bmat)
{
    __shared__ float Ks[128*32];
    __shared__ float Vs[128*32];
    int bh = blockIdx.y;
    int h  = bh & 3;
    int qrow = blockIdx.x * 128 + threadIdx.x;

    const float* qp = g_q + ((size_t)bh*HW + qrow)*DK;
    float q[32], o[32];
    #pragma unroll
    for (int d = 0; d < 32; d++) { q[d] = qp[d] * QK_SCALE; o[d] = 0.f; }
    float l = 0.f;

    const float* Brow = Bmat + ((size_t)h*HW + qrow)*KHW;
    const float* kg = g_k + (size_t)bh*KHW*DK;
    const float* vg = g_v + (size_t)bh*KHW*DK;

    for (int c0 = 0; c0 < KHW; c0 += 128) {
        __syncthreads();
        for (int e = threadIdx.x; e < 4096; e += 128) {
            Ks[e] = kg[c0*32 + e];
            Vs[e] = vg[c0*32 + e];
        }
        __syncthreads();
        for (int j = 0; j < 128; j++) {
            const float4* kr = (const float4*)(Ks + j*32);
            float s = 0.f;
            #pragma unroll
            for (int d4 = 0; d4 < 8; d4++) {
                float4 kk = kr[d4];
                s = fmaf(q[d4*4+0], kk.x, s);
                s = fmaf(q[d4*4+1], kk.y, s);
                s = fmaf(q[d4*4+2], kk.z, s);
                s = fmaf(q[d4*4+3], kk.w, s);
            }
            s += Brow[c0 + j];
            float p = __expf(s);           // logits are O(1) by construction
            l += p;
            const float4* vr = (const float4*)(Vs + j*32);
            #pragma unroll
            for (int d4 = 0; d4 < 8; d4++) {
                float4 vv = vr[d4];
                o[d4*4+0] = fmaf(p, vv.x, o[d4*4+0]);
                o[d4*4+1] = fmaf(p, vv.y, o[d4*4+1]);
                o[d4*4+2] = fmaf(p, vv.z, o[d4*4+2]);
                o[d4*4+3] = fmaf(p, vv.w, o[d4*4+3]);
            }
        }
    }
    float inv = 1.f / l;
    int b = bh >> 2;
    float* cp = g_ctx + ((size_t)b*HW + qrow)*HD + h*DK;
    #pragma unroll
    for (int d = 0; d < 32; d++) cp[d] = o[d]*inv;
}

// ---------------- stage 5: output projection + residual ----------------
// grid (HW/16, BATCH), 256 threads. out_flat = (ctx @ fco_w^T + b)_flat + x_flat.
__global__ void k_out(const float* __restrict__ x,
                      const float* __restrict__ fco_w,
                      const float* __restrict__ fco_b,
                      float* __restrict__ out)
{
    __shared__ float cs[16*128];   // 8 KB
    __shared__ float ws[128*65];   // [k][ch] padded, 32.5 KB
    int b   = blockIdx.y;
    int p0  = blockIdx.x * 16;
    int tid = threadIdx.x;

    for (int e = tid; e < 8192; e += 256) {
        int ch = e >> 7, k = e & 127;
        ws[k*65+ch] = fco_w[e];
    }
    const float* ctx = g_ctx + ((size_t)b*HW + p0)*HD;
    for (int e = tid; e < 2048; e += 256) cs[e] = ctx[e];
    __syncthreads();

    int ch = tid & 63;
    int pg = tid >> 6;             // 0..3, constant per warp
    float bias = fco_b[ch];
    #pragma unroll
    for (int pi = 0; pi < 4; pi++) {
        int pos = pg*4 + pi;
        float acc = bias;
        #pragma unroll
        for (int k = 0; k < 128; k++)
            acc = fmaf(cs[pos*128+k], ws[k*65+ch], acc);
        size_t oi = (size_t)b*(C*HW) + (size_t)(p0+pos)*64 + ch;
        out[oi] = acc + x[oi];
    }
}

// ---------------- launcher ----------------
extern "C" void kernel_launch(void* const* d_in, const int* in_sizes, int n_in,
                              void* d_out, int out_size)
{
    (void)n_in; (void)out_size;
    const float* x      = (const float*)d_in[0];
    const float* wk     = (const float*)d_in[1];
    const float* wv     = (const float*)d_in[2];
    const float* fcq_w  = (const float*)d_in[3];
    const float* fcq_b  = (const float*)d_in[4];
    const float* fck_w  = (const float*)d_in[5];
    const float* fck_b  = (const float*)d_in[6];
    const float* fcv_w  = (const float*)d_in[7];
    const float* fcv_b  = (const float*)d_in[8];
    const float* fco_w  = (const float*)d_in[9];
    const float* fco_b  = (const float*)d_in[10];
    const float* Bmat   = (const float*)d_in[11];
    float* out = (float*)d_out;

    k_zero<<<1, 1>>>();
    k_reduce<<<1024, 256>>>(x, in_sizes[0]);
    k_finalize<<<1, 1>>>();
    k_weff<<<dim3(512, 2), 128>>>(fck_w, wk, fcv_w, wv);
    k_qproj<<<dim3(HW/16, BATCH), 128>>>(x, fcq_w, fcq_b);
    k_kv<<<dim3(KHW/16, BATCH), 128>>>(x, fck_b, fcv_b);
    k_attn<<<dim3(HW/128, BATCH*HEADS), 128>>>(Bmat);
    k_out<<<dim3(HW/16, BATCH), 256>>>(x, fco_w, fco_b, out);
}

// round 2
// speedup vs baseline: 1.2564x; 1.2564x over previous
#include <cuda_runtime.h>
#include <math.h>

// ---------------- problem constants (fixed shapes) ----------------
#define BATCH 8
#define C     64
#define HH    64
#define WW    64
#define HW    4096          // 64*64
#define HEADS 4
#define DK    32
#define HD    128           // HEADS*DK
#define KHW   1024          // 32*32 (stride-2 output)
#define THETA 0.5f
#define EPS_LN 1e-5f
#define NTOT  (BATCH*C*HW)  // 2097152
#define QK_SCALE 0.17677669529663687f  // 1/sqrt(32)

// ---------------- device scratch (static, allowed) ----------------
__device__ double g_sums[2];
__device__ float  g_stats[2];                       // mean, rstd
__device__ float  g_weffk[512*128];                 // [ci*8+t][f]
__device__ float  g_weffv[512*128];
__device__ float  g_q[BATCH*HEADS*HW*DK];           // 16 MB
__device__ float  g_k[BATCH*HEADS*KHW*DK];          // 4 MB
__device__ float  g_v[BATCH*HEADS*KHW*DK];          // 4 MB
__device__ float  g_ctx[BATCH*HW*HD];               // 16 MB

// ---------------- stage 0: global mean/var ----------------
__global__ void k_zero()
{
    g_sums[0] = 0.0; g_sums[1] = 0.0;
}

__global__ void k_reduce(const float* __restrict__ x, int n)
{
    float s = 0.f, s2 = 0.f;
    for (int i = blockIdx.x*blockDim.x + threadIdx.x; i < n; i += gridDim.x*blockDim.x) {
        float v = x[i];
        s  += v;
        s2  = fmaf(v, v, s2);
    }
    #pragma unroll
    for (int off = 16; off; off >>= 1) {
        s  += __shfl_down_sync(0xffffffffu, s,  off);
        s2 += __shfl_down_sync(0xffffffffu, s2, off);
    }
    __shared__ float sh[2][8];
    int lane = threadIdx.x & 31, w = threadIdx.x >> 5;
    if (lane == 0) { sh[0][w] = s; sh[1][w] = s2; }
    __syncthreads();
    if (threadIdx.x == 0) {
        double ds = 0.0, ds2 = 0.0;
        for (int i = 0; i < 8; i++) { ds += (double)sh[0][i]; ds2 += (double)sh[1][i]; }
        atomicAdd(&g_sums[0], ds);
        atomicAdd(&g_sums[1], ds2);
    }
}

__global__ void k_finalize()
{
    double n = (double)NTOT;
    double m = g_sums[0] / n;
    double var = g_sums[1] / n - m*m;
    g_stats[0] = (float)m;
    g_stats[1] = (float)rsqrt(var + (double)EPS_LN);
}

// ---------------- stage 1: fold conv weights into FC: Weff ----------------
// Weff_T[(ci*8+t)*128 + f] = sum_co fc_w[f*64+co] * w8[co*512 + ci*8 + t]
// block = feature f (weight reads broadcast), threads = idx (coalesced w8 reads)
__global__ void k_weff(const float* __restrict__ fck_w, const float* __restrict__ wk,
                       const float* __restrict__ fcv_w, const float* __restrict__ wv)
{
    int f = blockIdx.x;                       // 0..127
    const float* fw = blockIdx.y ? fcv_w : fck_w;
    const float* w8 = blockIdx.y ? wv    : wk;
    float*      out = blockIdx.y ? g_weffv : g_weffk;
    int idx = threadIdx.x;                    // 0..511
    float acc = 0.f;
    #pragma unroll 16
    for (int co = 0; co < 64; co++)
        acc = fmaf(__ldg(&fw[f*64+co]), w8[co*512+idx], acc);
    out[idx*128+f] = acc;
}

// ---------------- stage 2: Q projection (with global LN) ----------------
// grid (HW/16, BATCH), 128 threads. Thread = feature f, 16 positions per block.
__global__ void k_qproj(const float* __restrict__ x,
                        const float* __restrict__ fcq_w,
                        const float* __restrict__ fcq_b)
{
    __shared__ float xs[64*16];     // [c][pos]
    __shared__ float ws[64*129];    // [c][f] padded
    int b   = blockIdx.y;
    int p0  = blockIdx.x * 16;
    int tid = threadIdx.x;
    float mean = g_stats[0], rstd = g_stats[1];

    for (int e = tid; e < 8192; e += 128) {
        int f = e >> 6, c = e & 63;
        ws[c*129+f] = fcq_w[e];
    }
    const float* xb = x + (size_t)b*C*HW;
    for (int e = tid; e < 1024; e += 128) {
        int c = e >> 4, pos = e & 15;
        xs[c*16+pos] = (xb[c*HW + p0 + pos] - mean) * rstd;
    }
    __syncthreads();

    int f = tid;
    float acc[16];
    float bias = fcq_b[f];
    #pragma unroll
    for (int i = 0; i < 16; i++) acc[i] = bias;
    for (int c = 0; c < 64; c++) {
        float wv_ = ws[c*129+f];
        #pragma unroll
        for (int i = 0; i < 16; i++) acc[i] = fmaf(wv_, xs[c*16+i], acc[i]);
    }
    int h = f >> 5, d = f & 31;
    float* qb = g_q + ((size_t)(b*HEADS+h)*HW)*DK + d;
    #pragma unroll
    for (int i = 0; i < 16; i++) qb[(size_t)(p0+i)*DK] = acc[i];
}

// ---------------- stage 3: PDC conv + K/V projection fused ----------------
// grid (KHW/16, BATCH), 128 threads. Thread = feature f, 16 output positions.
__global__ void k_kv(const float* __restrict__ x,
                     const float* __restrict__ fck_b,
                     const float* __restrict__ fcv_b)
{
    __shared__ float gs[16*512];    // 32 KB: [pos][ci*8+t]
    int b   = blockIdx.y;
    int p0  = blockIdx.x * 16;
    int tid = threadIdx.x;
    const float* xb = x + (size_t)b*C*HW;

    for (int e = tid; e < 8192; e += 128) {
        int pos = e >> 9;
        int idx = e & 511;
        int ci = idx >> 3, t = idx & 7;
        int pg = p0 + pos;
        int i = pg >> 5, j = pg & 31;
        int cy = i*2, cx = j*2;
        int k9 = (t < 4) ? t : t + 1;      // skip 3x3 center
        int ny = cy + (k9/3) - 1;
        int nx = cx + (k9%3) - 1;
        float ctr = xb[ci*HW + cy*WW + cx];
        float nb = 0.f;
        if (ny >= 0 && ny < HH && nx >= 0 && nx < WW)
            nb = xb[ci*HW + ny*WW + nx];
        gs[pos*512+idx] = nb - THETA*ctr;
    }
    __syncthreads();

    int f = tid;
    float ak[16], av[16];
    float bk = fck_b[f], bv = fcv_b[f];
    #pragma unroll
    for (int i = 0; i < 16; i++) { ak[i] = bk; av[i] = bv; }
    for (int idx = 0; idx < 512; idx++) {
        float wk_ = g_weffk[idx*128+f];
        float wv_ = g_weffv[idx*128+f];
        #pragma unroll
        for (int i = 0; i < 16; i++) {
            float gg = gs[i*512+idx];
            ak[i] = fmaf(wk_, gg, ak[i]);
            av[i] = fmaf(wv_, gg, av[i]);
        }
    }
    int h = f >> 5, d = f & 31;
    #pragma unroll
    for (int i = 0; i < 16; i++) {
        size_t addr = ((size_t)(b*HEADS+h)*KHW + p0 + i)*DK + d;
        g_k[addr] = ak[i];
        g_v[addr] = av[i];
    }
}

// ---------------- stage 4: attention (max-free online softmax) ----------------
// grid (HW/128, BATCH*HEADS), 128 threads; one query row per thread.
// 64-key tiles; K, V AND the bias B are staged through shared memory
// (B was previously read fully uncoalesced from gmem: ~4.3 GB of sector traffic).
__global__ void __launch_bounds__(128) k_attn(const float* __restrict__ Bmat)
{
    __shared__ float Ks[64*32];     // 8 KB
    __shared__ float Vs[64*32];     // 8 KB
    __shared__ float Bs[128*65];    // 33.3 KB, padded (stride 65) for conflict-free reads
    int bh = blockIdx.y;
    int h  = bh & 3;
    int q0 = blockIdx.x * 128;
    int tid = threadIdx.x;
    int qrow = q0 + tid;

    const float* qp = g_q + ((size_t)bh*HW + qrow)*DK;
    float q[32], o[32];
    #pragma unroll
    for (int d = 0; d < 32; d++) { q[d] = qp[d] * QK_SCALE; o[d] = 0.f; }
    float l = 0.f;

    const float* Bbase = Bmat + ((size_t)h*HW + q0)*KHW;
    const float* kg = g_k + (size_t)bh*KHW*DK;
    const float* vg = g_v + (size_t)bh*KHW*DK;

    for (int c0 = 0; c0 < KHW; c0 += 64) {
        __syncthreads();
        for (int e = tid; e < 2048; e += 128) {
            Ks[e] = kg[c0*32 + e];
            Vs[e] = vg[c0*32 + e];
        }
        // coalesced B tile load: 128 qrows x 64 keys
        for (int e = tid; e < 8192; e += 128) {
            int qr = e >> 6, j = e & 63;
            Bs[qr*65 + j] = Bbase[(size_t)qr*KHW + c0 + j];
        }
        __syncthreads();
        const float* brow = Bs + tid*65;
        for (int j = 0; j < 64; j++) {
            const float4* kr = (const float4*)(Ks + j*32);
            float s = brow[j];
            #pragma unroll
            for (int d4 = 0; d4 < 8; d4++) {
                float4 kk = kr[d4];
                s = fmaf(q[d4*4+0], kk.x, s);
                s = fmaf(q[d4*4+1], kk.y, s);
                s = fmaf(q[d4*4+2], kk.z, s);
                s = fmaf(q[d4*4+3], kk.w, s);
            }
            float p = __expf(s);           // logits are O(1) by construction
            l += p;
            const float4* vr = (const float4*)(Vs + j*32);
            #pragma unroll
            for (int d4 = 0; d4 < 8; d4++) {
                float4 vv = vr[d4];
                o[d4*4+0] = fmaf(p, vv.x, o[d4*4+0]);
                o[d4*4+1] = fmaf(p, vv.y, o[d4*4+1]);
                o[d4*4+2] = fmaf(p, vv.z, o[d4*4+2]);
                o[d4*4+3] = fmaf(p, vv.w, o[d4*4+3]);
            }
        }
    }
    float inv = 1.f / l;
    int b = bh >> 2;
    float* cp = g_ctx + ((size_t)b*HW + qrow)*HD + h*DK;
    #pragma unroll
    for (int d = 0; d < 32; d++) cp[d] = o[d]*inv;
}

// ---------------- stage 5: output projection + residual ----------------
// grid (HW/16, BATCH), 256 threads. out_flat = (ctx @ fco_w^T + b)_flat + x_flat.
__global__ void k_out(const float* __restrict__ x,
                      const float* __restrict__ fco_w,
                      const float* __restrict__ fco_b,
                      float* __restrict__ out)
{
    __shared__ float cs[16*128];   // 8 KB
    __shared__ float ws[128*65];   // [k][ch] padded, 32.5 KB
    int b   = blockIdx.y;
    int p0  = blockIdx.x * 16;
    int tid = threadIdx.x;

    for (int e = tid; e < 8192; e += 256) {
        int ch = e >> 7, k = e & 127;
        ws[k*65+ch] = fco_w[e];
    }
    const float* ctx = g_ctx + ((size_t)b*HW + p0)*HD;
    for (int e = tid; e < 2048; e += 256) cs[e] = ctx[e];
    __syncthreads();

    int ch = tid & 63;
    int pg = tid >> 6;             // 0..3, constant per warp
    float bias = fco_b[ch];
    #pragma unroll
    for (int pi = 0; pi < 4; pi++) {
        int pos = pg*4 + pi;
        float acc = bias;
        #pragma unroll
        for (int k = 0; k < 128; k++)
            acc = fmaf(cs[pos*128+k], ws[k*65+ch], acc);
        size_t oi = (size_t)b*(C*HW) + (size_t)(p0+pos)*64 + ch;
        out[oi] = acc + x[oi];
    }
}

// ---------------- launcher ----------------
extern "C" void kernel_launch(void* const* d_in, const int* in_sizes, int n_in,
                              void* d_out, int out_size)
{
    (void)n_in; (void)out_size;
    const float* x      = (const float*)d_in[0];
    const float* wk     = (const float*)d_in[1];
    const float* wv     = (const float*)d_in[2];
    const float* fcq_w  = (const float*)d_in[3];
    const float* fcq_b  = (const float*)d_in[4];
    const float* fck_w  = (const float*)d_in[5];
    const float* fck_b  = (const float*)d_in[6];
    const float* fcv_w  = (const float*)d_in[7];
    const float* fcv_b  = (const float*)d_in[8];
    const float* fco_w  = (const float*)d_in[9];
    const float* fco_b  = (const float*)d_in[10];
    const float* Bmat   = (const float*)d_in[11];
    float* out = (float*)d_out;

    k_zero<<<1, 1>>>();
    k_reduce<<<1024, 256>>>(x, in_sizes[0]);
    k_finalize<<<1, 1>>>();
    k_weff<<<dim3(128, 2), 512>>>(fck_w, wk, fcv_w, wv);
    k_qproj<<<dim3(HW/16, BATCH), 128>>>(x, fcq_w, fcq_b);
    k_kv<<<dim3(KHW/16, BATCH), 128>>>(x, fck_b, fcv_b);
    k_attn<<<dim3(HW/128, BATCH*HEADS), 128>>>(Bmat);
    k_out<<<dim3(HW/16, BATCH), 256>>>(x, fco_w, fco_b, out);
}

// round 3
// speedup vs baseline: 1.4354x; 1.1425x over previous
#include <cuda_runtime.h>
#include <math.h>

// ---------------- problem constants (fixed shapes) ----------------
#define BATCH 8
#define C     64
#define HH    64
#define WW    64
#define HW    4096          // 64*64
#define HEADS 4
#define DK    32
#define HD    128           // HEADS*DK
#define KHW   1024          // 32*32 (stride-2 output)
#define THETA 0.5f
#define EPS_LN 1e-5f
#define NTOT  (BATCH*C*HW)  // 2097152
#define QK_SCALE 0.17677669529663687f  // 1/sqrt(32)

typedef unsigned long long ull;

// packed fp32x2 helpers (FFMA2 — only reachable via explicit PTX)
__device__ __forceinline__ void fma2(ull& d, ull a, ull b, ull c) {
    asm("fma.rn.f32x2 %0, %1, %2, %3;" : "=l"(d) : "l"(a), "l"(b), "l"(c));
}
__device__ __forceinline__ ull pack2(float lo, float hi) {
    ull r; asm("mov.b64 %0, {%1, %2};" : "=l"(r) : "f"(lo), "f"(hi)); return r;
}
__device__ __forceinline__ void unpack2(float& lo, float& hi, ull v) {
    asm("mov.b64 {%0, %1}, %2;" : "=f"(lo), "=f"(hi) : "l"(v));
}

// ---------------- device scratch (static, allowed) ----------------
__device__ double g_sums[2];
__device__ float  g_stats[2];                       // mean, rstd
__device__ float  g_weffk[512*128];                 // [ci*8+t][f]
__device__ float  g_weffv[512*128];
__device__ float  g_q[BATCH*HEADS*HW*DK];           // 16 MB
__device__ float  g_k[BATCH*HEADS*KHW*DK];          // 4 MB
__device__ float  g_v[BATCH*HEADS*KHW*DK];          // 4 MB
__device__ float  g_ctx[BATCH*HW*HD];               // 16 MB

// ---------------- stage 0: global mean/var ----------------
__global__ void k_zero()
{
    g_sums[0] = 0.0; g_sums[1] = 0.0;
}

__global__ void k_reduce(const float* __restrict__ x, int n)
{
    float s = 0.f, s2 = 0.f;
    for (int i = blockIdx.x*blockDim.x + threadIdx.x; i < n; i += gridDim.x*blockDim.x) {
        float v = x[i];
        s  += v;
        s2  = fmaf(v, v, s2);
    }
    #pragma unroll
    for (int off = 16; off; off >>= 1) {
        s  += __shfl_down_sync(0xffffffffu, s,  off);
        s2 += __shfl_down_sync(0xffffffffu, s2, off);
    }
    __shared__ float sh[2][8];
    int lane = threadIdx.x & 31, w = threadIdx.x >> 5;
    if (lane == 0) { sh[0][w] = s; sh[1][w] = s2; }
    __syncthreads();
    if (threadIdx.x == 0) {
        double ds = 0.0, ds2 = 0.0;
        for (int i = 0; i < 8; i++) { ds += (double)sh[0][i]; ds2 += (double)sh[1][i]; }
        atomicAdd(&g_sums[0], ds);
        atomicAdd(&g_sums[1], ds2);
    }
}

__global__ void k_finalize()
{
    double n = (double)NTOT;
    double m = g_sums[0] / n;
    double var = g_sums[1] / n - m*m;
    g_stats[0] = (float)m;
    g_stats[1] = (float)rsqrt(var + (double)EPS_LN);
}

// ---------------- stage 1: fold conv weights into FC: Weff ----------------
__global__ void k_weff(const float* __restrict__ fck_w, const float* __restrict__ wk,
                       const float* __restrict__ fcv_w, const float* __restrict__ wv)
{
    int f = blockIdx.x;                       // 0..127
    const float* fw = blockIdx.y ? fcv_w : fck_w;
    const float* w8 = blockIdx.y ? wv    : wk;
    float*      out = blockIdx.y ? g_weffv : g_weffk;
    int idx = threadIdx.x;                    // 0..511
    float acc = 0.f;
    #pragma unroll 16
    for (int co = 0; co < 64; co++)
        acc = fmaf(__ldg(&fw[f*64+co]), w8[co*512+idx], acc);
    out[idx*128+f] = acc;
}

// ---------------- stage 2: Q projection (with global LN), f32x2 packed ----------------
// grid (HW/16, BATCH), 128 threads. Thread = feature f, 16 positions per block.
__global__ void k_qproj(const float* __restrict__ x,
                        const float* __restrict__ fcq_w,
                        const float* __restrict__ fcq_b)
{
    __shared__ float xs[64*16];     // [c][pos] — positions contiguous (packable)
    __shared__ float ws[64*129];    // [c][f] padded
    int b   = blockIdx.y;
    int p0  = blockIdx.x * 16;
    int tid = threadIdx.x;
    float mean = g_stats[0], rstd = g_stats[1];

    for (int e = tid; e < 8192; e += 128) {
        int f = e >> 6, c = e & 63;
        ws[c*129+f] = fcq_w[e];
    }
    const float* xb = x + (size_t)b*C*HW;
    for (int e = tid; e < 1024; e += 128) {
        int c = e >> 4, pos = e & 15;
        xs[c*16+pos] = (xb[c*HW + p0 + pos] - mean) * rstd;
    }
    __syncthreads();

    int f = tid;
    float bias = fcq_b[f];
    ull acc2[8];
    #pragma unroll
    for (int i = 0; i < 8; i++) acc2[i] = pack2(bias, bias);
    for (int c = 0; c < 64; c++) {
        float w_ = ws[c*129+f];
        ull w2 = pack2(w_, w_);
        const ull* xr = (const ull*)(xs + c*16);
        #pragma unroll
        for (int i = 0; i < 8; i++) fma2(acc2[i], w2, xr[i], acc2[i]);
    }
    int h = f >> 5, d = f & 31;
    float* qb = g_q + ((size_t)(b*HEADS+h)*HW)*DK + d;
    #pragma unroll
    for (int i = 0; i < 8; i++) {
        float a0, a1; unpack2(a0, a1, acc2[i]);
        qb[(size_t)(p0+2*i)*DK]   = a0;
        qb[(size_t)(p0+2*i+1)*DK] = a1;
    }
}

// ---------------- stage 3: PDC conv + K/V projection fused ----------------
__global__ void k_kv(const float* __restrict__ x,
                     const float* __restrict__ fck_b,
                     const float* __restrict__ fcv_b)
{
    __shared__ float gs[16*512];    // 32 KB: [pos][ci*8+t]
    int b   = blockIdx.y;
    int p0  = blockIdx.x * 16;
    int tid = threadIdx.x;
    const float* xb = x + (size_t)b*C*HW;

    for (int e = tid; e < 8192; e += 128) {
        int pos = e >> 9;
        int idx = e & 511;
        int ci = idx >> 3, t = idx & 7;
        int pg = p0 + pos;
        int i = pg >> 5, j = pg & 31;
        int cy = i*2, cx = j*2;
        int k9 = (t < 4) ? t : t + 1;      // skip 3x3 center
        int ny = cy + (k9/3) - 1;
        int nx = cx + (k9%3) - 1;
        float ctr = xb[ci*HW + cy*WW + cx];
        float nb = 0.f;
        if (ny >= 0 && ny < HH && nx >= 0 && nx < WW)
            nb = xb[ci*HW + ny*WW + nx];
        gs[pos*512+idx] = nb - THETA*ctr;
    }
    __syncthreads();

    int f = tid;
    float ak[16], av[16];
    float bk = fck_b[f], bv = fcv_b[f];
    #pragma unroll
    for (int i = 0; i < 16; i++) { ak[i] = bk; av[i] = bv; }
    for (int idx = 0; idx < 512; idx++) {
        float wk_ = g_weffk[idx*128+f];
        float wv_ = g_weffv[idx*128+f];
        #pragma unroll
        for (int i = 0; i < 16; i++) {
            float gg = gs[i*512+idx];
            ak[i] = fmaf(wk_, gg, ak[i]);
            av[i] = fmaf(wv_, gg, av[i]);
        }
    }
    int h = f >> 5, d = f & 31;
    #pragma unroll
    for (int i = 0; i < 16; i++) {
        size_t addr = ((size_t)(b*HEADS+h)*KHW + p0 + i)*DK + d;
        g_k[addr] = ak[i];
        g_v[addr] = av[i];
    }
}

// ---------------- stage 4: attention, f32x2 packed (FFMA2) ----------------
// grid (HW/128, BATCH*HEADS), 128 threads; one query row per thread.
__global__ void __launch_bounds__(128) k_attn(const float* __restrict__ Bmat)
{
    __shared__ float Ks[64*32];     // 8 KB
    __shared__ float Vs[64*32];     // 8 KB
    __shared__ float Bs[128*65];    // 33.3 KB, padded for conflict-free row reads
    int bh = blockIdx.y;
    int h  = bh & 3;
    int q0 = blockIdx.x * 128;
    int tid = threadIdx.x;
    int qrow = q0 + tid;

    const float4* qp4 = (const float4*)(g_q + ((size_t)bh*HW + qrow)*DK);
    ull q2[16], o2[16];
    #pragma unroll
    for (int i = 0; i < 8; i++) {
        float4 t = qp4[i];
        q2[2*i]   = pack2(t.x*QK_SCALE, t.y*QK_SCALE);
        q2[2*i+1] = pack2(t.z*QK_SCALE, t.w*QK_SCALE);
    }
    #pragma unroll
    for (int i = 0; i < 16; i++) o2[i] = 0ull;   // bits of (0.f, 0.f)
    float l = 0.f;

    const float* Bbase = Bmat + ((size_t)h*HW + q0)*KHW;
    const float* kg = g_k + (size_t)bh*KHW*DK;
    const float* vg = g_v + (size_t)bh*KHW*DK;

    for (int c0 = 0; c0 < KHW; c0 += 64) {
        __syncthreads();
        for (int e = tid; e < 2048; e += 128) {
            Ks[e] = kg[c0*32 + e];
            Vs[e] = vg[c0*32 + e];
        }
        for (int e = tid; e < 8192; e += 128) {
            int qr = e >> 6, j = e & 63;
            Bs[qr*65 + j] = Bbase[(size_t)qr*KHW + c0 + j];
        }
        __syncthreads();
        const float* brow = Bs + tid*65;
        for (int j = 0; j < 64; j++) {
            const ulonglong2* kr = (const ulonglong2*)(Ks + j*32);
            ull sa = 0ull, sb = 0ull;
            #pragma unroll
            for (int i2 = 0; i2 < 8; i2++) {
                ulonglong2 kk = kr[i2];
                fma2(sa, q2[2*i2],   kk.x, sa);
                fma2(sb, q2[2*i2+1], kk.y, sb);
            }
            float s0, s1, s2_, s3;
            unpack2(s0, s1, sa);
            unpack2(s2_, s3, sb);
            float s = (s0 + s1) + (s2_ + s3) + brow[j];
            float p = __expf(s);           // logits are O(1) by construction
            l += p;
            ull p2 = pack2(p, p);
            const ulonglong2* vr = (const ulonglong2*)(Vs + j*32);
            #pragma unroll
            for (int i2 = 0; i2 < 8; i2++) {
                ulonglong2 vv = vr[i2];
                fma2(o2[2*i2],   p2, vv.x, o2[2*i2]);
                fma2(o2[2*i2+1], p2, vv.y, o2[2*i2+1]);
            }
        }
    }
    float inv = 1.f / l;
    int b = bh >> 2;
    float* cp = g_ctx + ((size_t)b*HW + qrow)*HD + h*DK;
    #pragma unroll
    for (int i = 0; i < 16; i++) {
        float a0, a1; unpack2(a0, a1, o2[i]);
        cp[2*i]   = a0 * inv;
        cp[2*i+1] = a1 * inv;
    }
}

// ---------------- stage 5: output projection + residual ----------------
__global__ void k_out(const float* __restrict__ x,
                      const float* __restrict__ fco_w,
                      const float* __restrict__ fco_b,
                      float* __restrict__ out)
{
    __shared__ float cs[16*128];   // 8 KB
    __shared__ float ws[128*65];   // [k][ch] padded, 32.5 KB
    int b   = blockIdx.y;
    int p0  = blockIdx.x * 16;
    int tid = threadIdx.x;

    for (int e = tid; e < 8192; e += 256) {
        int ch = e >> 7, k = e & 127;
        ws[k*65+ch] = fco_w[e];
    }
    const float* ctx = g_ctx + ((size_t)b*HW + p0)*HD;
    for (int e = tid; e < 2048; e += 256) cs[e] = ctx[e];
    __syncthreads();

    int ch = tid & 63;
    int pg = tid >> 6;             // 0..3, constant per warp
    float bias = fco_b[ch];
    #pragma unroll
    for (int pi = 0; pi < 4; pi++) {
        int pos = pg*4 + pi;
        float acc = bias;
        #pragma unroll
        for (int k = 0; k < 128; k++)
            acc = fmaf(cs[pos*128+k], ws[k*65+ch], acc);
        size_t oi = (size_t)b*(C*HW) + (size_t)(p0+pos)*64 + ch;
        out[oi] = acc + x[oi];
    }
}

// ---------------- launcher ----------------
extern "C" void kernel_launch(void* const* d_in, const int* in_sizes, int n_in,
                              void* d_out, int out_size)
{
    (void)n_in; (void)out_size;
    const float* x      = (const float*)d_in[0];
    const float* wk     = (const float*)d_in[1];
    const float* wv     = (const float*)d_in[2];
    const float* fcq_w  = (const float*)d_in[3];
    const float* fcq_b  = (const float*)d_in[4];
    const float* fck_w  = (const float*)d_in[5];
    const float* fck_b  = (const float*)d_in[6];
    const float* fcv_w  = (const float*)d_in[7];
    const float* fcv_b  = (const float*)d_in[8];
    const float* fco_w  = (const float*)d_in[9];
    const float* fco_b  = (const float*)d_in[10];
    const float* Bmat   = (const float*)d_in[11];
    float* out = (float*)d_out;

    k_zero<<<1, 1>>>();
    k_reduce<<<1024, 256>>>(x, in_sizes[0]);
    k_finalize<<<1, 1>>>();
    k_weff<<<dim3(128, 2), 512>>>(fck_w, wk, fcv_w, wv);
    k_qproj<<<dim3(HW/16, BATCH), 128>>>(x, fcq_w, fcq_b);
    k_kv<<<dim3(KHW/16, BATCH), 128>>>(x, fck_b, fcv_b);
    k_attn<<<dim3(HW/128, BATCH*HEADS), 128>>>(Bmat);
    k_out<<<dim3(HW/16, BATCH), 256>>>(x, fco_w, fco_b, out);
}

// round 4
// speedup vs baseline: 1.6015x; 1.1157x over previous
#include <cuda_runtime.h>
#include <math.h>

// ---------------- problem constants (fixed shapes) ----------------
#define BATCH 8
#define C     64
#define HH    64
#define WW    64
#define HW    4096          // 64*64
#define HEADS 4
#define DK    32
#define HD    128           // HEADS*DK
#define KHW   1024          // 32*32 (stride-2 output)
#define THETA 0.5f
#define EPS_LN 1e-5f
#define NTOT  (BATCH*C*HW)  // 2097152
#define QK_SCALE 0.17677669529663687f  // 1/sqrt(32)

typedef unsigned long long ull;

// packed fp32x2 helpers (FFMA2/FADD2 — only reachable via explicit PTX)
__device__ __forceinline__ void fma2(ull& d, ull a, ull b, ull c) {
    asm("fma.rn.f32x2 %0, %1, %2, %3;" : "=l"(d) : "l"(a), "l"(b), "l"(c));
}
__device__ __forceinline__ void add2(ull& d, ull a, ull b) {
    asm("add.rn.f32x2 %0, %1, %2;" : "=l"(d) : "l"(a), "l"(b));
}
__device__ __forceinline__ ull pack2(float lo, float hi) {
    ull r; asm("mov.b64 %0, {%1, %2};" : "=l"(r) : "f"(lo), "f"(hi)); return r;
}
__device__ __forceinline__ void unpack2(float& lo, float& hi, ull v) {
    asm("mov.b64 {%0, %1}, %2;" : "=f"(lo), "=f"(hi) : "l"(v));
}

// ---------------- device scratch (static, allowed) ----------------
__device__ float  g_part_s[512];
__device__ float  g_part_s2[512];
__device__ float  g_stats[2];                       // mean, rstd
__device__ float  g_weffk[512*128];                 // [ci*8+t][f]
__device__ float  g_weffv[512*128];
__device__ float  g_q[BATCH*HEADS*HW*DK];           // 16 MB
__device__ float  g_k[BATCH*HEADS*KHW*DK];          // 4 MB
__device__ float  g_v[BATCH*HEADS*KHW*DK];          // 4 MB
__device__ float  g_ctx[BATCH*HW*HD];               // 16 MB

// ---------------- launch 0: per-block partial sums (deterministic) ----------------
__global__ void k_part(const float* __restrict__ x)
{
    float s = 0.f, s2 = 0.f;
    int base = blockIdx.x * (NTOT/512);
    for (int i = threadIdx.x; i < NTOT/512; i += 256) {
        float v = x[base + i];
        s  += v;
        s2  = fmaf(v, v, s2);
    }
    #pragma unroll
    for (int off = 16; off; off >>= 1) {
        s  += __shfl_down_sync(0xffffffffu, s,  off);
        s2 += __shfl_down_sync(0xffffffffu, s2, off);
    }
    __shared__ float sh[2][8];
    int lane = threadIdx.x & 31, w = threadIdx.x >> 5;
    if (lane == 0) { sh[0][w] = s; sh[1][w] = s2; }
    __syncthreads();
    if (threadIdx.x == 0) {
        float ts = 0.f, ts2 = 0.f;
        for (int i = 0; i < 8; i++) { ts += sh[0][i]; ts2 += sh[1][i]; }
        g_part_s[blockIdx.x]  = ts;
        g_part_s2[blockIdx.x] = ts2;
    }
}

// ---------------- launch 1: stats finalize (block 0) + weff fold (blocks 1..256) ----------------
__global__ void k_stats_weff(const float* __restrict__ fck_w, const float* __restrict__ wk,
                             const float* __restrict__ fcv_w, const float* __restrict__ wv)
{
    if (blockIdx.x == 0) {
        __shared__ double sh[512], sh2[512];
        int t = threadIdx.x;
        sh[t]  = (double)g_part_s[t];
        sh2[t] = (double)g_part_s2[t];
        __syncthreads();
        for (int o = 256; o; o >>= 1) {
            if (t < o) { sh[t] += sh[t+o]; sh2[t] += sh2[t+o]; }
            __syncthreads();
        }
        if (t == 0) {
            double n = (double)NTOT;
            double m = sh[0] / n;
            double var = sh2[0] / n - m*m;
            g_stats[0] = (float)m;
            g_stats[1] = (float)rsqrt(var + (double)EPS_LN);
        }
        return;
    }
    // weff: Weff_T[(ci*8+t)*128 + f] = sum_co fc_w[f*64+co] * w8[co*512 + ci*8 + t]
    int b2 = blockIdx.x - 1;          // 0..255
    int f  = b2 & 127;
    const float* fw = (b2 >> 7) ? fcv_w : fck_w;
    const float* w8 = (b2 >> 7) ? wv    : wk;
    float*      out = (b2 >> 7) ? g_weffv : g_weffk;
    int idx = threadIdx.x;            // 0..511
    float acc = 0.f;
    #pragma unroll 16
    for (int co = 0; co < 64; co++)
        acc = fmaf(__ldg(&fw[f*64+co]), w8[co*512+idx], acc);
    out[idx*128+f] = acc;
}

// ---------------- launch 2: merged Q projection + PDC-conv K/V projection ----------------
// blockIdx.x < 256 : qproj tile (16 positions), else kv tile (16 positions)
__global__ void __launch_bounds__(128) k_qkv(const float* __restrict__ x,
                    const float* __restrict__ fcq_w, const float* __restrict__ fcq_b,
                    const float* __restrict__ fck_b, const float* __restrict__ fcv_b)
{
    __shared__ float sm[9280];        // qproj: xs[1024]+ws[8256]; kv: gs[8192]
    int b   = blockIdx.y;
    int tid = threadIdx.x;

    if (blockIdx.x < 256) {
        // ---- Q projection with global LN, f32x2 packed ----
        float* xs = sm;               // [c][pos], 64*16
        float* ws = sm + 1024;        // [c][f] padded 129
        int p0 = blockIdx.x * 16;
        float mean = g_stats[0], rstd = g_stats[1];

        for (int e = tid; e < 8192; e += 128) {
            int f = e >> 6, c = e & 63;
            ws[c*129+f] = fcq_w[e];
        }
        const float* xb = x + (size_t)b*C*HW;
        for (int e = tid; e < 1024; e += 128) {
            int c = e >> 4, pos = e & 15;
            xs[c*16+pos] = (xb[c*HW + p0 + pos] - mean) * rstd;
        }
        __syncthreads();

        int f = tid;
        float bias = fcq_b[f];
        ull acc2[8];
        #pragma unroll
        for (int i = 0; i < 8; i++) acc2[i] = pack2(bias, bias);
        for (int c = 0; c < 64; c++) {
            float w_ = ws[c*129+f];
            ull w2 = pack2(w_, w_);
            const ull* xr = (const ull*)(xs + c*16);
            #pragma unroll
            for (int i = 0; i < 8; i++) fma2(acc2[i], w2, xr[i], acc2[i]);
        }
        int h = f >> 5, d = f & 31;
        float* qb = g_q + ((size_t)(b*HEADS+h)*HW)*DK + d;
        #pragma unroll
        for (int i = 0; i < 8; i++) {
            float a0, a1; unpack2(a0, a1, acc2[i]);
            qb[(size_t)(p0+2*i)*DK]   = a0;
            qb[(size_t)(p0+2*i+1)*DK] = a1;
        }
    } else {
        // ---- PDC conv gather + K/V projection, f32x2 packed ----
        float* gs = sm;               // [idx][pos] : 512*16
        int p0 = (blockIdx.x - 256) * 16;
        const float* xb = x + (size_t)b*C*HW;

        for (int e = tid; e < 8192; e += 128) {
            int idx = e >> 4;
            int pos = e & 15;
            int ci = idx >> 3, t = idx & 7;
            int pg = p0 + pos;
            int i = pg >> 5, j = pg & 31;
            int cy = i*2, cx = j*2;
            int k9 = (t < 4) ? t : t + 1;      // skip 3x3 center
            int ny = cy + (k9/3) - 1;
            int nx = cx + (k9%3) - 1;
            float ctr = xb[ci*HW + cy*WW + cx];
            float nb = 0.f;
            if (ny >= 0 && ny < HH && nx >= 0 && nx < WW)
                nb = xb[ci*HW + ny*WW + nx];
            gs[idx*16+pos] = nb - THETA*ctr;
        }
        __syncthreads();

        int f = tid;
        float bk = fck_b[f], bv = fcv_b[f];
        ull ak2[8], av2[8];
        #pragma unroll
        for (int i = 0; i < 8; i++) { ak2[i] = pack2(bk, bk); av2[i] = pack2(bv, bv); }
        #pragma unroll 4
        for (int idx = 0; idx < 512; idx++) {
            float wk_ = g_weffk[idx*128+f];
            float wv_ = g_weffv[idx*128+f];
            ull wk2 = pack2(wk_, wk_);
            ull wv2 = pack2(wv_, wv_);
            const ull* gr = (const ull*)(gs + idx*16);
            #pragma unroll
            for (int i = 0; i < 8; i++) {
                ull gg = gr[i];
                fma2(ak2[i], wk2, gg, ak2[i]);
                fma2(av2[i], wv2, gg, av2[i]);
            }
        }
        int h = f >> 5, d = f & 31;
        #pragma unroll
        for (int i = 0; i < 8; i++) {
            float k0, k1, v0, v1;
            unpack2(k0, k1, ak2[i]);
            unpack2(v0, v1, av2[i]);
            size_t a0 = ((size_t)(b*HEADS+h)*KHW + p0 + 2*i)*DK + d;
            g_k[a0]      = k0;  g_k[a0 + DK] = k1;
            g_v[a0]      = v0;  g_v[a0 + DK] = v1;
        }
    }
}

// ---------------- launch 3: attention, f32x2 packed, 2 keys/iter ----------------
// grid (HW/128, BATCH*HEADS), 128 threads; one query row per thread.
__global__ void __launch_bounds__(128, 4) k_attn(const float* __restrict__ Bmat)
{
    __shared__ float Ks[64*32];     // 8 KB
    __shared__ float Vs[64*32];     // 8 KB
    __shared__ float Bs[128*66];    // 33 KB, stride 66 (even -> 8B-aligned float2)
    int bh = blockIdx.y;
    int h  = bh & 3;
    int q0 = blockIdx.x * 128;
    int tid = threadIdx.x;
    int qrow = q0 + tid;

    const float4* qp4 = (const float4*)(g_q + ((size_t)bh*HW + qrow)*DK);
    ull q2[16], o2[16];
    #pragma unroll
    for (int i = 0; i < 8; i++) {
        float4 t = qp4[i];
        q2[2*i]   = pack2(t.x*QK_SCALE, t.y*QK_SCALE);
        q2[2*i+1] = pack2(t.z*QK_SCALE, t.w*QK_SCALE);
    }
    #pragma unroll
    for (int i = 0; i < 16; i++) o2[i] = 0ull;
    float l = 0.f;

    const float* Bbase = Bmat + ((size_t)h*HW + q0)*KHW;
    const float* kg = g_k + (size_t)bh*KHW*DK;
    const float* vg = g_v + (size_t)bh*KHW*DK;

    for (int c0 = 0; c0 < KHW; c0 += 64) {
        __syncthreads();
        for (int e = tid; e < 2048; e += 128) {
            Ks[e] = kg[c0*32 + e];
            Vs[e] = vg[c0*32 + e];
        }
        for (int e = tid; e < 8192; e += 128) {
            int qr = e >> 6, j = e & 63;
            Bs[qr*66 + j] = Bbase[(size_t)qr*KHW + c0 + j];
        }
        __syncthreads();
        const float* brow = Bs + tid*66;
        for (int j = 0; j < 64; j += 2) {
            const ulonglong2* kr0 = (const ulonglong2*)(Ks + j*32);
            const ulonglong2* kr1 = (const ulonglong2*)(Ks + j*32 + 32);
            ull sa0 = 0ull, sb0 = 0ull, sa1 = 0ull, sb1 = 0ull;
            #pragma unroll
            for (int i2 = 0; i2 < 8; i2++) {
                ulonglong2 k0 = kr0[i2];
                ulonglong2 k1 = kr1[i2];
                fma2(sa0, q2[2*i2],   k0.x, sa0);
                fma2(sb0, q2[2*i2+1], k0.y, sb0);
                fma2(sa1, q2[2*i2],   k1.x, sa1);
                fma2(sb1, q2[2*i2+1], k1.y, sb1);
            }
            ull sc0, sc1;
            add2(sc0, sa0, sb0);
            add2(sc1, sa1, sb1);
            float u0, v0, u1, v1;
            unpack2(u0, v0, sc0);
            unpack2(u1, v1, sc1);
            float2 bb = *(const float2*)(brow + j);
            float p0 = __expf(u0 + v0 + bb.x);
            float p1 = __expf(u1 + v1 + bb.y);
            l += (p0 + p1);
            ull p02 = pack2(p0, p0);
            ull p12 = pack2(p1, p1);
            const ulonglong2* vr0 = (const ulonglong2*)(Vs + j*32);
            const ulonglong2* vr1 = (const ulonglong2*)(Vs + j*32 + 32);
            #pragma unroll
            for (int i2 = 0; i2 < 8; i2++) {
                ulonglong2 w0 = vr0[i2];
                ulonglong2 w1 = vr1[i2];
                fma2(o2[2*i2],   p02, w0.x, o2[2*i2]);
                fma2(o2[2*i2+1], p02, w0.y, o2[2*i2+1]);
                fma2(o2[2*i2],   p12, w1.x, o2[2*i2]);
                fma2(o2[2*i2+1], p12, w1.y, o2[2*i2+1]);
            }
        }
    }
    float inv = 1.f / l;
    int b = bh >> 2;
    float* cp = g_ctx + ((size_t)b*HW + qrow)*HD + h*DK;
    #pragma unroll
    for (int i = 0; i < 16; i++) {
        float a0, a1; unpack2(a0, a1, o2[i]);
        cp[2*i]   = a0 * inv;
        cp[2*i+1] = a1 * inv;
    }
}

// ---------------- launch 4: output projection + residual, f32x2 packed ----------------
__global__ void k_out(const float* __restrict__ x,
                      const float* __restrict__ fco_w,
                      const float* __restrict__ fco_b,
                      float* __restrict__ out)
{
    __shared__ float cs[16*128];    // [pos][k] 8 KB
    __shared__ float ws2[64*130];   // [ch][k] stride 130 (even), 33.3 KB
    int b   = blockIdx.y;
    int p0  = blockIdx.x * 16;
    int tid = threadIdx.x;

    for (int e = tid; e < 8192; e += 256) {
        int ch = e >> 7, k = e & 127;
        ws2[ch*130+k] = fco_w[e];
    }
    const float* ctx = g_ctx + ((size_t)b*HW + p0)*HD;
    for (int e = tid; e < 2048; e += 256) cs[e] = ctx[e];
    __syncthreads();

    int ch = tid & 63;
    int pg = tid >> 6;              // 0..3
    ull acc2[4];
    #pragma unroll
    for (int pi = 0; pi < 4; pi++) acc2[pi] = 0ull;
    const ull* wr = (const ull*)(ws2 + ch*130);
    #pragma unroll 4
    for (int kp = 0; kp < 64; kp++) {
        ull w2 = wr[kp];
        #pragma unroll
        for (int pi = 0; pi < 4; pi++) {
            ull c2 = *(const ull*)(cs + (pg*4+pi)*128 + 2*kp);
            fma2(acc2[pi], w2, c2, acc2[pi]);
        }
    }
    float bias = fco_b[ch];
    #pragma unroll
    for (int pi = 0; pi < 4; pi++) {
        float a0, a1; unpack2(a0, a1, acc2[pi]);
        int pos = pg*4 + pi;
        size_t oi = (size_t)b*(C*HW) + (size_t)(p0+pos)*64 + ch;
        out[oi] = (a0 + a1) + bias + x[oi];
    }
}

// ---------------- launcher (exactly 5 launches; k_attn is launch idx 3) ----------------
extern "C" void kernel_launch(void* const* d_in, const int* in_sizes, int n_in,
                              void* d_out, int out_size)
{
    (void)n_in; (void)out_size; (void)in_sizes;
    const float* x      = (const float*)d_in[0];
    const float* wk     = (const float*)d_in[1];
    const float* wv     = (const float*)d_in[2];
    const float* fcq_w  = (const float*)d_in[3];
    const float* fcq_b  = (const float*)d_in[4];
    const float* fck_w  = (const float*)d_in[5];
    const float* fck_b  = (const float*)d_in[6];
    const float* fcv_w  = (const float*)d_in[7];
    const float* fcv_b  = (const float*)d_in[8];
    const float* fco_w  = (const float*)d_in[9];
    const float* fco_b  = (const float*)d_in[10];
    const float* Bmat   = (const float*)d_in[11];
    float* out = (float*)d_out;

    k_part<<<512, 256>>>(x);
    k_stats_weff<<<257, 512>>>(fck_w, wk, fcv_w, wv);
    k_qkv<<<dim3(256+64, BATCH), 128>>>(x, fcq_w, fcq_b, fck_b, fcv_b);
    k_attn<<<dim3(HW/128, BATCH*HEADS), 128>>>(Bmat);
    k_out<<<dim3(HW/16, BATCH), 256>>>(x, fco_w, fco_b, out);
}

// round 5
// speedup vs baseline: 1.6689x; 1.0421x over previous
#include <cuda_runtime.h>
#include <math.h>

// ---------------- problem constants (fixed shapes) ----------------
#define BATCH 8
#define C     64
#define HH    64
#define WW    64
#define HW    4096          // 64*64
#define HEADS 4
#define DK    32
#define HD    128           // HEADS*DK
#define KHW   1024          // 32*32 (stride-2 output)
#define THETA 0.5f
#define EPS_LN 1e-5f
#define NTOT  (BATCH*C*HW)  // 2097152
#define QK_SCALE 0.17677669529663687f  // 1/sqrt(32)

typedef unsigned long long ull;

// packed fp32x2 helpers (FFMA2/FADD2 — only reachable via explicit PTX)
__device__ __forceinline__ void fma2(ull& d, ull a, ull b, ull c) {
    asm("fma.rn.f32x2 %0, %1, %2, %3;" : "=l"(d) : "l"(a), "l"(b), "l"(c));
}
__device__ __forceinline__ void add2(ull& d, ull a, ull b) {
    asm("add.rn.f32x2 %0, %1, %2;" : "=l"(d) : "l"(a), "l"(b));
}
__device__ __forceinline__ ull pack2(float lo, float hi) {
    ull r; asm("mov.b64 %0, {%1, %2};" : "=l"(r) : "f"(lo), "f"(hi)); return r;
}
__device__ __forceinline__ void unpack2(float& lo, float& hi, ull v) {
    asm("mov.b64 {%0, %1}, %2;" : "=f"(lo), "=f"(hi) : "l"(v));
}

// ---------------- device scratch (static, allowed) ----------------
__device__ float  g_part_s[512];
__device__ float  g_part_s2[512];
__device__ float  g_stats[2];                       // mean, rstd
__device__ float  g_weffk[512*128];                 // [ci*8+t][f]
__device__ float  g_weffv[512*128];
__device__ float  g_q[BATCH*HEADS*HW*DK];           // 16 MB
__device__ float  g_k[BATCH*HEADS*KHW*DK];          // 4 MB
__device__ float  g_v[BATCH*HEADS*KHW*DK];          // 4 MB
__device__ float  g_ctx[BATCH*HW*HD];               // 16 MB

// ---------------- launch 0: per-block partial sums (deterministic) ----------------
__global__ void k_part(const float* __restrict__ x)
{
    float s = 0.f, s2 = 0.f;
    int base = blockIdx.x * (NTOT/512);
    for (int i = threadIdx.x; i < NTOT/512; i += 256) {
        float v = x[base + i];
        s  += v;
        s2  = fmaf(v, v, s2);
    }
    #pragma unroll
    for (int off = 16; off; off >>= 1) {
        s  += __shfl_down_sync(0xffffffffu, s,  off);
        s2 += __shfl_down_sync(0xffffffffu, s2, off);
    }
    __shared__ float sh[2][8];
    int lane = threadIdx.x & 31, w = threadIdx.x >> 5;
    if (lane == 0) { sh[0][w] = s; sh[1][w] = s2; }
    __syncthreads();
    if (threadIdx.x == 0) {
        float ts = 0.f, ts2 = 0.f;
        for (int i = 0; i < 8; i++) { ts += sh[0][i]; ts2 += sh[1][i]; }
        g_part_s[blockIdx.x]  = ts;
        g_part_s2[blockIdx.x] = ts2;
    }
}

// ---------------- launch 1: stats finalize (block 0) + weff fold (blocks 1..256) ----------------
__global__ void k_stats_weff(const float* __restrict__ fck_w, const float* __restrict__ wk,
                             const float* __restrict__ fcv_w, const float* __restrict__ wv)
{
    if (blockIdx.x == 0) {
        __shared__ double sh[512], sh2[512];
        int t = threadIdx.x;
        sh[t]  = (double)g_part_s[t];
        sh2[t] = (double)g_part_s2[t];
        __syncthreads();
        for (int o = 256; o; o >>= 1) {
            if (t < o) { sh[t] += sh[t+o]; sh2[t] += sh2[t+o]; }
            __syncthreads();
        }
        if (t == 0) {
            double n = (double)NTOT;
            double m = sh[0] / n;
            double var = sh2[0] / n - m*m;
            g_stats[0] = (float)m;
            g_stats[1] = (float)rsqrt(var + (double)EPS_LN);
        }
        return;
    }
    int b2 = blockIdx.x - 1;          // 0..255
    int f  = b2 & 127;
    const float* fw = (b2 >> 7) ? fcv_w : fck_w;
    const float* w8 = (b2 >> 7) ? wv    : wk;
    float*      out = (b2 >> 7) ? g_weffv : g_weffk;
    int idx = threadIdx.x;            // 0..511
    float acc = 0.f;
    #pragma unroll 16
    for (int co = 0; co < 64; co++)
        acc = fmaf(__ldg(&fw[f*64+co]), w8[co*512+idx], acc);
    out[idx*128+f] = acc;
}

// ---------------- launch 2: merged Q projection + PDC-conv K/V projection ----------------
__global__ void __launch_bounds__(128) k_qkv(const float* __restrict__ x,
                    const float* __restrict__ fcq_w, const float* __restrict__ fcq_b,
                    const float* __restrict__ fck_b, const float* __restrict__ fcv_b)
{
    __shared__ float sm[9280];        // qproj: xs[1024]+ws[8256]; kv: gs[8192]
    int b   = blockIdx.y;
    int tid = threadIdx.x;

    if (blockIdx.x < 256) {
        float* xs = sm;               // [c][pos], 64*16
        float* ws = sm + 1024;        // [c][f] padded 129
        int p0 = blockIdx.x * 16;
        float mean = g_stats[0], rstd = g_stats[1];

        for (int e = tid; e < 8192; e += 128) {
            int f = e >> 6, c = e & 63;
            ws[c*129+f] = fcq_w[e];
        }
        const float* xb = x + (size_t)b*C*HW;
        for (int e = tid; e < 1024; e += 128) {
            int c = e >> 4, pos = e & 15;
            xs[c*16+pos] = (xb[c*HW + p0 + pos] - mean) * rstd;
        }
        __syncthreads();

        int f = tid;
        float bias = fcq_b[f];
        ull acc2[8];
        #pragma unroll
        for (int i = 0; i < 8; i++) acc2[i] = pack2(bias, bias);
        for (int c = 0; c < 64; c++) {
            float w_ = ws[c*129+f];
            ull w2 = pack2(w_, w_);
            const ull* xr = (const ull*)(xs + c*16);
            #pragma unroll
            for (int i = 0; i < 8; i++) fma2(acc2[i], w2, xr[i], acc2[i]);
        }
        int h = f >> 5, d = f & 31;
        float* qb = g_q + ((size_t)(b*HEADS+h)*HW)*DK + d;
        #pragma unroll
        for (int i = 0; i < 8; i++) {
            float a0, a1; unpack2(a0, a1, acc2[i]);
            qb[(size_t)(p0+2*i)*DK]   = a0;
            qb[(size_t)(p0+2*i+1)*DK] = a1;
        }
    } else {
        float* gs = sm;               // [idx][pos] : 512*16
        int p0 = (blockIdx.x - 256) * 16;
        const float* xb = x + (size_t)b*C*HW;

        for (int e = tid; e < 8192; e += 128) {
            int idx = e >> 4;
            int pos = e & 15;
            int ci = idx >> 3, t = idx & 7;
            int pg = p0 + pos;
            int i = pg >> 5, j = pg & 31;
            int cy = i*2, cx = j*2;
            int k9 = (t < 4) ? t : t + 1;      // skip 3x3 center
            int ny = cy + (k9/3) - 1;
            int nx = cx + (k9%3) - 1;
            float ctr = xb[ci*HW + cy*WW + cx];
            float nb = 0.f;
            if (ny >= 0 && ny < HH && nx >= 0 && nx < WW)
                nb = xb[ci*HW + ny*WW + nx];
            gs[idx*16+pos] = nb - THETA*ctr;
        }
        __syncthreads();

        int f = tid;
        float bk = fck_b[f], bv = fcv_b[f];
        ull ak2[8], av2[8];
        #pragma unroll
        for (int i = 0; i < 8; i++) { ak2[i] = pack2(bk, bk); av2[i] = pack2(bv, bv); }
        #pragma unroll 4
        for (int idx = 0; idx < 512; idx++) {
            float wk_ = g_weffk[idx*128+f];
            float wv_ = g_weffv[idx*128+f];
            ull wk2 = pack2(wk_, wk_);
            ull wv2 = pack2(wv_, wv_);
            const ull* gr = (const ull*)(gs + idx*16);
            #pragma unroll
            for (int i = 0; i < 8; i++) {
                ull gg = gr[i];
                fma2(ak2[i], wk2, gg, ak2[i]);
                fma2(av2[i], wv2, gg, av2[i]);
            }
        }
        int h = f >> 5, d = f & 31;
        #pragma unroll
        for (int i = 0; i < 8; i++) {
            float k0, k1, v0, v1;
            unpack2(k0, k1, ak2[i]);
            unpack2(v0, v1, av2[i]);
            size_t a0 = ((size_t)(b*HEADS+h)*KHW + p0 + 2*i)*DK + d;
            g_k[a0]      = k0;  g_k[a0 + DK] = k1;
            g_v[a0]      = v0;  g_v[a0 + DK] = v1;
        }
    }
}

// ---------------- launch 3: attention — 4-way dim-split, 4 queries/thread ----------------
// 128 threads = 32 groups of 4; group handles 4 query rows; thread owns 8 dims.
// Per key per thread: 2 LDS.128 (K) + 2 (V) + 1 LDS.32 (bias) serving 4 query-keys.
__global__ void __launch_bounds__(128, 4) k_attn(const float* __restrict__ Bmat)
{
    __shared__ float Ks[64*32];     // 8 KB
    __shared__ float Vs[64*32];     // 8 KB
    __shared__ float Bs[128*65];    // 32.5 KB, odd stride -> conflict-free scattered reads
    int bh = blockIdx.y;
    int h  = bh & 3;
    int q0 = blockIdx.x * 128;
    int tid = threadIdx.x;
    int dq    = tid & 3;            // dim-quarter: dims [dq*8, dq*8+8)
    int qbase = tid & ~3;           // first of this group's 4 query rows (relative)

    // load Q: 4 queries x 8 dims (pre-scaled)
    ull q2[4][4], o2[4][4];
    const float* qg = g_q + ((size_t)bh*HW + q0 + qbase)*DK + dq*8;
    #pragma unroll
    for (int qi = 0; qi < 4; qi++) {
        float4 a = *(const float4*)(qg + qi*DK);
        float4 c = *(const float4*)(qg + qi*DK + 4);
        q2[qi][0] = pack2(a.x*QK_SCALE, a.y*QK_SCALE);
        q2[qi][1] = pack2(a.z*QK_SCALE, a.w*QK_SCALE);
        q2[qi][2] = pack2(c.x*QK_SCALE, c.y*QK_SCALE);
        q2[qi][3] = pack2(c.z*QK_SCALE, c.w*QK_SCALE);
        o2[qi][0] = o2[qi][1] = o2[qi][2] = o2[qi][3] = 0ull;
    }
    ull l01 = 0ull, l23 = 0ull;

    const float* Bbase = Bmat + ((size_t)h*HW + q0)*KHW;
    const float* kg = g_k + (size_t)bh*KHW*DK;
    const float* vg = g_v + (size_t)bh*KHW*DK;
    int brow_off = (qbase + dq)*65;
    int dqodd = dq & 1;

    for (int c0 = 0; c0 < KHW; c0 += 64) {
        __syncthreads();
        for (int e = tid; e < 2048; e += 128) {
            Ks[e] = kg[c0*32 + e];
            Vs[e] = vg[c0*32 + e];
        }
        for (int e = tid; e < 8192; e += 128) {
            int qr = e >> 6, j = e & 63;
            Bs[qr*65 + j] = Bbase[(size_t)qr*KHW + c0 + j];
        }
        __syncthreads();
        #pragma unroll 2
        for (int j = 0; j < 64; j++) {
            const ulonglong2* kr = (const ulonglong2*)(Ks + j*32 + dq*8);
            ulonglong2 ka = kr[0];           // dims 0..3 of my slice
            ulonglong2 kb = kr[1];           // dims 4..7
            float v[4];
            #pragma unroll
            for (int qi = 0; qi < 4; qi++) {
                ull s = 0ull;
                fma2(s, q2[qi][0], ka.x, s);
                fma2(s, q2[qi][1], ka.y, s);
                fma2(s, q2[qi][2], kb.x, s);
                fma2(s, q2[qi][3], kb.y, s);
                float lo, hi; unpack2(lo, hi, s);
                v[qi] = lo + hi;
            }
            v[dq] += Bs[brow_off + j];       // bias counted exactly once across group
            ull P01 = pack2(v[0], v[1]);
            ull P23 = pack2(v[2], v[3]);
            // round 1 (xor 1): even dq collects pair01, odd collects pair23
            ull send1 = dqodd ? P01 : P23;
            ull keep1 = dqodd ? P23 : P01;
            ull recv1 = __shfl_xor_sync(0xffffffffu, send1, 1);
            ull S1; add2(S1, keep1, recv1);
            // round 2 (xor 2): full sums
            ull recv2 = __shfl_xor_sync(0xffffffffu, S1, 2);
            ull S2; add2(S2, S1, recv2);
            float sA, sB; unpack2(sA, sB, S2);
            ull Pmine = pack2(__expf(sA), __expf(sB));
            ull Pother = __shfl_xor_sync(0xffffffffu, Pmine, 1);
            ull Q01 = dqodd ? Pother : Pmine;    // (p0,p1)
            ull Q23 = dqodd ? Pmine : Pother;    // (p2,p3)
            add2(l01, l01, Q01);
            add2(l23, l23, Q23);
            float p0, p1, p2, p3;
            unpack2(p0, p1, Q01);
            unpack2(p2, p3, Q23);
            ull pp0 = pack2(p0, p0), pp1 = pack2(p1, p1);
            ull pp2 = pack2(p2, p2), pp3 = pack2(p3, p3);
            const ulonglong2* vr = (const ulonglong2*)(Vs + j*32 + dq*8);
            ulonglong2 va = vr[0], vb = vr[1];
            fma2(o2[0][0], pp0, va.x, o2[0][0]);
            fma2(o2[0][1], pp0, va.y, o2[0][1]);
            fma2(o2[0][2], pp0, vb.x, o2[0][2]);
            fma2(o2[0][3], pp0, vb.y, o2[0][3]);
            fma2(o2[1][0], pp1, va.x, o2[1][0]);
            fma2(o2[1][1], pp1, va.y, o2[1][1]);
            fma2(o2[1][2], pp1, vb.x, o2[1][2]);
            fma2(o2[1][3], pp1, vb.y, o2[1][3]);
            fma2(o2[2][0], pp2, va.x, o2[2][0]);
            fma2(o2[2][1], pp2, va.y, o2[2][1]);
            fma2(o2[2][2], pp2, vb.x, o2[2][2]);
            fma2(o2[2][3], pp2, vb.y, o2[2][3]);
            fma2(o2[3][0], pp3, va.x, o2[3][0]);
            fma2(o2[3][1], pp3, va.y, o2[3][1]);
            fma2(o2[3][2], pp3, vb.x, o2[3][2]);
            fma2(o2[3][3], pp3, vb.y, o2[3][3]);
        }
    }
    float l0, l1, l2, l3;
    unpack2(l0, l1, l01);
    unpack2(l2, l3, l23);
    float linv[4] = {1.f/l0, 1.f/l1, 1.f/l2, 1.f/l3};
    int b = bh >> 2;
    float* cp = g_ctx + ((size_t)b*HW + q0 + qbase)*HD + h*DK + dq*8;
    #pragma unroll
    for (int qi = 0; qi < 4; qi++) {
        float r0,r1,r2,r3,r4,r5,r6,r7;
        unpack2(r0, r1, o2[qi][0]);
        unpack2(r2, r3, o2[qi][1]);
        unpack2(r4, r5, o2[qi][2]);
        unpack2(r6, r7, o2[qi][3]);
        float4* dst = (float4*)(cp + (size_t)qi*HD);
        dst[0] = make_float4(r0*linv[qi], r1*linv[qi], r2*linv[qi], r3*linv[qi]);
        dst[1] = make_float4(r4*linv[qi], r5*linv[qi], r6*linv[qi], r7*linv[qi]);
    }
}

// ---------------- launch 4: output projection + residual, f32x2 packed ----------------
__global__ void k_out(const float* __restrict__ x,
                      const float* __restrict__ fco_w,
                      const float* __restrict__ fco_b,
                      float* __restrict__ out)
{
    __shared__ float cs[16*128];    // [pos][k] 8 KB
    __shared__ float ws2[64*130];   // [ch][k] stride 130 (even), 33.3 KB
    int b   = blockIdx.y;
    int p0  = blockIdx.x * 16;
    int tid = threadIdx.x;

    for (int e = tid; e < 8192; e += 256) {
        int ch = e >> 7, k = e & 127;
        ws2[ch*130+k] = fco_w[e];
    }
    const float* ctx = g_ctx + ((size_t)b*HW + p0)*HD;
    for (int e = tid; e < 2048; e += 256) cs[e] = ctx[e];
    __syncthreads();

    int ch = tid & 63;
    int pg = tid >> 6;              // 0..3
    ull acc2[4];
    #pragma unroll
    for (int pi = 0; pi < 4; pi++) acc2[pi] = 0ull;
    const ull* wr = (const ull*)(ws2 + ch*130);
    #pragma unroll 4
    for (int kp = 0; kp < 64; kp++) {
        ull w2 = wr[kp];
        #pragma unroll
        for (int pi = 0; pi < 4; pi++) {
            ull c2 = *(const ull*)(cs + (pg*4+pi)*128 + 2*kp);
            fma2(acc2[pi], w2, c2, acc2[pi]);
        }
    }
    float bias = fco_b[ch];
    #pragma unroll
    for (int pi = 0; pi < 4; pi++) {
        float a0, a1; unpack2(a0, a1, acc2[pi]);
        int pos = pg*4 + pi;
        size_t oi = (size_t)b*(C*HW) + (size_t)(p0+pos)*64 + ch;
        out[oi] = (a0 + a1) + bias + x[oi];
    }
}

// ---------------- launcher (5 launches; k_attn is launch idx 3) ----------------
extern "C" void kernel_launch(void* const* d_in, const int* in_sizes, int n_in,
                              void* d_out, int out_size)
{
    (void)n_in; (void)out_size; (void)in_sizes;
    const float* x      = (const float*)d_in[0];
    const float* wk     = (const float*)d_in[1];
    const float* wv     = (const float*)d_in[2];
    const float* fcq_w  = (const float*)d_in[3];
    const float* fcq_b  = (const float*)d_in[4];
    const float* fck_w  = (const float*)d_in[5];
    const float* fck_b  = (const float*)d_in[6];
    const float* fcv_w  = (const float*)d_in[7];
    const float* fcv_b  = (const float*)d_in[8];
    const float* fco_w  = (const float*)d_in[9];
    const float* fco_b  = (const float*)d_in[10];
    const float* Bmat   = (const float*)d_in[11];
    float* out = (float*)d_out;

    k_part<<<512, 256>>>(x);
    k_stats_weff<<<257, 512>>>(fck_w, wk, fcv_w, wv);
    k_qkv<<<dim3(256+64, BATCH), 128>>>(x, fcq_w, fcq_b, fck_b, fcv_b);
    k_attn<<<dim3(HW/128, BATCH*HEADS), 128>>>(Bmat);
    k_out<<<dim3(HW/16, BATCH), 256>>>(x, fco_w, fco_b, out);
}

// round 8
// speedup vs baseline: 4.1283x; 2.4737x over previous
#include <cuda_runtime.h>
#include <cuda_bf16.h>
#include <math.h>
#include <stdint.h>

// ---------------- problem constants (fixed shapes) ----------------
#define BATCH 8
#define C     64
#define HH    64
#define WW    64
#define HW    4096          // 64*64
#define HEADS 4
#define DK    32
#define HD    128           // HEADS*DK
#define KHW   1024          // 32*32 (stride-2 output)
#define THETA 0.5f
#define EPS_LN 1e-5f
#define NTOT  (BATCH*C*HW)  // 2097152
#define QK_SCALE 0.17677669529663687f  // 1/sqrt(32)

typedef unsigned long long ull;

// packed fp32x2 helpers
__device__ __forceinline__ void fma2(ull& d, ull a, ull b, ull c) {
    asm("fma.rn.f32x2 %0, %1, %2, %3;" : "=l"(d) : "l"(a), "l"(b), "l"(c));
}
__device__ __forceinline__ ull pack2(float lo, float hi) {
    ull r; asm("mov.b64 %0, {%1, %2};" : "=l"(r) : "f"(lo), "f"(hi)); return r;
}
__device__ __forceinline__ void unpack2(float& lo, float& hi, ull v) {
    asm("mov.b64 {%0, %1}, %2;" : "=f"(lo), "=f"(hi) : "l"(v));
}
__device__ __forceinline__ uint32_t bf16x2_of(float a, float b) {
    uint32_t r;
    asm("cvt.rn.satfinite.bf16x2.f32 %0, %1, %2;" : "=r"(r) : "f"(b), "f"(a));
    return r;   // lo=a, hi=b
}

// warp mma: D(16x8,f32) += A(16x16,bf16,row) * B(16x8,bf16,col)
__device__ __forceinline__ void mma_bf16(float* d, const uint32_t* a,
                                         uint32_t b0, uint32_t b1) {
    asm volatile("mma.sync.aligned.m16n8k16.row.col.f32.bf16.bf16.f32 "
        "{%0,%1,%2,%3}, {%4,%5,%6,%7}, {%8,%9}, {%0,%1,%2,%3};"
        : "+f"(d[0]), "+f"(d[1]), "+f"(d[2]), "+f"(d[3])
        : "r"(a[0]), "r"(a[1]), "r"(a[2]), "r"(a[3]), "r"(b0), "r"(b1));
}

// ---------------- device scratch (static, allowed) ----------------
__device__ float  g_part_s[512];
__device__ float  g_part_s2[512];
__device__ float  g_stats[2];
__device__ float  g_weffk[512*128];
__device__ float  g_weffv[512*128];
__device__ __nv_bfloat16 g_qh[BATCH*HEADS*HW*DK];   // pre-scaled Q, bf16, [bh][q][d]
__device__ __nv_bfloat16 g_kh[BATCH*HEADS*KHW*DK];  // K bf16 [bh][key][d]
__device__ __nv_bfloat16 g_vT[BATCH*HEADS*DK*KHW];  // V bf16 transposed [bh][d][key]
__device__ float  g_ctx[BATCH*HW*HD];

// ---------------- launch 0: per-block partial sums (deterministic) ----------------
__global__ void k_part(const float* __restrict__ x)
{
    float s = 0.f, s2 = 0.f;
    int base = blockIdx.x * (NTOT/512);
    for (int i = threadIdx.x; i < NTOT/512; i += 256) {
        float v = x[base + i];
        s  += v;
        s2  = fmaf(v, v, s2);
    }
    #pragma unroll
    for (int off = 16; off; off >>= 1) {
        s  += __shfl_down_sync(0xffffffffu, s,  off);
        s2 += __shfl_down_sync(0xffffffffu, s2, off);
    }
    __shared__ float sh[2][8];
    int lane = threadIdx.x & 31, w = threadIdx.x >> 5;
    if (lane == 0) { sh[0][w] = s; sh[1][w] = s2; }
    __syncthreads();
    if (threadIdx.x == 0) {
        float ts = 0.f, ts2 = 0.f;
        for (int i = 0; i < 8; i++) { ts += sh[0][i]; ts2 += sh[1][i]; }
        g_part_s[blockIdx.x]  = ts;
        g_part_s2[blockIdx.x] = ts2;
    }
}

// ---------------- launch 1: stats finalize (block 0) + weff fold (blocks 1..256) ----------------
__global__ void k_stats_weff(const float* __restrict__ fck_w, const float* __restrict__ wk,
                             const float* __restrict__ fcv_w, const float* __restrict__ wv)
{
    if (blockIdx.x == 0) {
        __shared__ double sh[512], sh2[512];
        int t = threadIdx.x;
        sh[t]  = (double)g_part_s[t];
        sh2[t] = (double)g_part_s2[t];
        __syncthreads();
        for (int o = 256; o; o >>= 1) {
            if (t < o) { sh[t] += sh[t+o]; sh2[t] += sh2[t+o]; }
            __syncthreads();
        }
        if (t == 0) {
            double n = (double)NTOT;
            double m = sh[0] / n;
            double var = sh2[0] / n - m*m;
            g_stats[0] = (float)m;
            g_stats[1] = (float)rsqrt(var + (double)EPS_LN);
        }
        return;
    }
    int b2 = blockIdx.x - 1;          // 0..255
    int f  = b2 & 127;
    const float* fw = (b2 >> 7) ? fcv_w : fck_w;
    const float* w8 = (b2 >> 7) ? wv    : wk;
    float*      out = (b2 >> 7) ? g_weffv : g_weffk;
    int idx = threadIdx.x;            // 0..511
    float acc = 0.f;
    #pragma unroll 16
    for (int co = 0; co < 64; co++)
        acc = fmaf(__ldg(&fw[f*64+co]), w8[co*512+idx], acc);
    out[idx*128+f] = acc;
}

// ---------------- launch 2: merged Q projection + PDC-conv K/V projection (bf16 out) ----------------
__global__ void __launch_bounds__(128) k_qkv(const float* __restrict__ x,
                    const float* __restrict__ fcq_w, const float* __restrict__ fcq_b,
                    const float* __restrict__ fck_b, const float* __restrict__ fcv_b)
{
    __shared__ float sm[9280];
    int b   = blockIdx.y;
    int tid = threadIdx.x;

    if (blockIdx.x < 256) {
        float* xs = sm;               // [c][pos], 64*16
        float* ws = sm + 1024;        // [c][f] padded 129
        int p0 = blockIdx.x * 16;
        float mean = g_stats[0], rstd = g_stats[1];

        for (int e = tid; e < 8192; e += 128) {
            int f = e >> 6, c = e & 63;
            ws[c*129+f] = fcq_w[e];
        }
        const float* xb = x + (size_t)b*C*HW;
        for (int e = tid; e < 1024; e += 128) {
            int c = e >> 4, pos = e & 15;
            xs[c*16+pos] = (xb[c*HW + p0 + pos] - mean) * rstd;
        }
        __syncthreads();

        int f = tid;
        float bias = fcq_b[f];
        ull acc2[8];
        #pragma unroll
        for (int i = 0; i < 8; i++) acc2[i] = pack2(bias, bias);
        for (int c = 0; c < 64; c++) {
            float w_ = ws[c*129+f];
            ull w2 = pack2(w_, w_);
            const ull* xr = (const ull*)(xs + c*16);
            #pragma unroll
            for (int i = 0; i < 8; i++) fma2(acc2[i], w2, xr[i], acc2[i]);
        }
        int h = f >> 5, d = f & 31;
        __nv_bfloat16* qb = g_qh + ((size_t)(b*HEADS+h)*HW + p0)*DK + d;
        #pragma unroll
        for (int i = 0; i < 8; i++) {
            float a0, a1; unpack2(a0, a1, acc2[i]);
            qb[(size_t)(2*i)*DK]   = __float2bfloat16(a0 * QK_SCALE);
            qb[(size_t)(2*i+1)*DK] = __float2bfloat16(a1 * QK_SCALE);
        }
    } else {
        float* gs = sm;               // [idx][pos] : 512*16
        int p0 = (blockIdx.x - 256) * 16;
        const float* xb = x + (size_t)b*C*HW;

        for (int e = tid; e < 8192; e += 128) {
            int idx = e >> 4;
            int pos = e & 15;
            int ci = idx >> 3, t = idx & 7;
            int pg = p0 + pos;
            int i = pg >> 5, j = pg & 31;
            int cy = i*2, cx = j*2;
            int k9 = (t < 4) ? t : t + 1;      // skip 3x3 center
            int ny = cy + (k9/3) - 1;
            int nx = cx + (k9%3) - 1;
            float ctr = xb[ci*HW + cy*WW + cx];
            float nb = 0.f;
            if (ny >= 0 && ny < HH && nx >= 0 && nx < WW)
                nb = xb[ci*HW + ny*WW + nx];
            gs[idx*16+pos] = nb - THETA*ctr;
        }
        __syncthreads();

        int f = tid;
        float bk = fck_b[f], bv = fcv_b[f];
        ull ak2[8], av2[8];
        #pragma unroll
        for (int i = 0; i < 8; i++) { ak2[i] = pack2(bk, bk); av2[i] = pack2(bv, bv); }
        #pragma unroll 4
        for (int idx = 0; idx < 512; idx++) {
            float wk_ = g_weffk[idx*128+f];
            float wv_ = g_weffv[idx*128+f];
            ull wk2 = pack2(wk_, wk_);
            ull wv2 = pack2(wv_, wv_);
            const ull* gr = (const ull*)(gs + idx*16);
            #pragma unroll
            for (int i = 0; i < 8; i++) {
                ull gg = gr[i];
                fma2(ak2[i], wk2, gg, ak2[i]);
                fma2(av2[i], wv2, gg, av2[i]);
            }
        }
        int h = f >> 5, d = f & 31;
        __nv_bfloat16* kb = g_kh + ((size_t)(b*HEADS+h)*KHW + p0)*DK + d;
        uint32_t* vb = (uint32_t*)(g_vT + ((size_t)(b*HEADS+h)*DK + d)*KHW + p0);
        #pragma unroll
        for (int i = 0; i < 8; i++) {
            float k0, k1, v0, v1;
            unpack2(k0, k1, ak2[i]);
            unpack2(v0, v1, av2[i]);
            kb[(size_t)(2*i)*DK]   = __float2bfloat16(k0);
            kb[(size_t)(2*i+1)*DK] = __float2bfloat16(k1);
            vb[i] = bf16x2_of(v0, v1);   // keys p0+2i, p0+2i+1 at dim d
        }
    }
}

// ---------------- launch 3: attention via mma.sync (bf16 HMMA, fp32 accum) ----------------
// CTA: 128 q-rows x one (b,h). 4 warps, warp w owns rows q0+32w..+31.
// Loop over 16 key tiles of 64. S and P stay in registers; P never touches smem.
#define KT 64
__global__ void __launch_bounds__(128) k_attn(const float* __restrict__ Bmat)
{
    __shared__ __align__(16) __nv_bfloat16 Ksm[KT][40];     // keys x dims (pad 40)
    __shared__ __align__(16) __nv_bfloat16 Vsm[DK][KT+8];   // dims x keys (pad 72)
    int tid = threadIdx.x;
    int w = tid >> 5, l = tid & 31;
    int g = l >> 2, t = l & 3;
    int bh = blockIdx.y, h = bh & 3;
    int q0 = blockIdx.x * 128 + w * 32;

    // Q a-frags (once): [mtile][kchunk][4]
    uint32_t qa[2][2][4];
    const __nv_bfloat16* Qb = g_qh + ((size_t)bh*HW + q0)*DK;
    #pragma unroll
    for (int mt = 0; mt < 2; mt++)
        #pragma unroll
        for (int kc = 0; kc < 2; kc++) {
            int r0 = mt*16 + g;
            qa[mt][kc][0] = *(const uint32_t*)(Qb + (size_t)r0*DK     + kc*16 + 2*t);
            qa[mt][kc][1] = *(const uint32_t*)(Qb + (size_t)(r0+8)*DK + kc*16 + 2*t);
            qa[mt][kc][2] = *(const uint32_t*)(Qb + (size_t)r0*DK     + kc*16 + 8 + 2*t);
            qa[mt][kc][3] = *(const uint32_t*)(Qb + (size_t)(r0+8)*DK + kc*16 + 8 + 2*t);
        }

    float o[2][4][4];                 // [mtile][dim-block][frag]
    float lsum[2][2];                 // [mtile][row g / g+8]
    #pragma unroll
    for (int mt = 0; mt < 2; mt++) {
        lsum[mt][0] = lsum[mt][1] = 0.f;
        #pragma unroll
        for (int db = 0; db < 4; db++)
            o[mt][db][0] = o[mt][db][1] = o[mt][db][2] = o[mt][db][3] = 0.f;
    }

    const float* Bb = Bmat + (size_t)h*HW*KHW;
    const uint32_t* kgl = (const uint32_t*)(g_kh + (size_t)bh*KHW*DK);
    const __nv_bfloat16* vgl = g_vT + (size_t)bh*DK*KHW;

    for (int c0 = 0; c0 < KHW; c0 += KT) {
        __syncthreads();
        // K tile: 64 keys x 16 u32 (row-major [key][dim]) = 1024 u32
        #pragma unroll
        for (int i = 0; i < 8; i++) {
            int e = tid + i*128;
            int r = e >> 4, c = e & 15;
            ((uint32_t*)&Ksm[r][0])[c] = kgl[(size_t)(c0 + r)*16 + c];
        }
        // V tile: 32 dims x 32 u32 (transposed [dim][key], 64 keys) = 1024 u32
        #pragma unroll
        for (int i = 0; i < 8; i++) {
            int e = tid + i*128;
            int d = e >> 5, c = e & 31;
            ((uint32_t*)&Vsm[d][0])[c] =
                ((const uint32_t*)(vgl + (size_t)d*KHW + c0))[c];
        }
        __syncthreads();

        #pragma unroll
        for (int half = 0; half < 2; half++) {
            int c32 = half * 32;
            // ---- S = Q K^T over 32 keys ----
            float s[2][4][4];
            #pragma unroll
            for (int mt = 0; mt < 2; mt++)
                #pragma unroll
                for (int nb = 0; nb < 4; nb++)
                    s[mt][nb][0] = s[mt][nb][1] = s[mt][nb][2] = s[mt][nb][3] = 0.f;
            #pragma unroll
            for (int nb = 0; nb < 4; nb++) {
                int key = c32 + 8*nb + g;
                uint32_t b0 = *(const uint32_t*)&Ksm[key][2*t];
                uint32_t b1 = *(const uint32_t*)&Ksm[key][8  + 2*t];
                uint32_t b2 = *(const uint32_t*)&Ksm[key][16 + 2*t];
                uint32_t b3 = *(const uint32_t*)&Ksm[key][24 + 2*t];
                #pragma unroll
                for (int mt = 0; mt < 2; mt++) {
                    mma_bf16(s[mt][nb], qa[mt][0], b0, b1);
                    mma_bf16(s[mt][nb], qa[mt][1], b2, b3);
                }
            }
            // ---- epilogue: +bias, exp, l, pack P (A-frags of next gemm) ----
            uint32_t pa[2][2][4];     // [mtile][kchunk16][4]
            #pragma unroll
            for (int mt = 0; mt < 2; mt++)
                #pragma unroll
                for (int nb = 0; nb < 4; nb++) {
                    int row = q0 + mt*16 + g;
                    size_t bidx = (size_t)row*KHW + c0 + c32 + 8*nb + 2*t;
                    float2 bv0 = *(const float2*)(Bb + bidx);
                    float2 bv1 = *(const float2*)(Bb + bidx + (size_t)8*KHW);
                    float p0 = __expf(s[mt][nb][0] + bv0.x);
                    float p1 = __expf(s[mt][nb][1] + bv0.y);
                    float p2 = __expf(s[mt][nb][2] + bv1.x);
                    float p3 = __expf(s[mt][nb][3] + bv1.y);
                    lsum[mt][0] += (p0 + p1);
                    lsum[mt][1] += (p2 + p3);
                    int u = nb >> 1, odd = nb & 1;
                    pa[mt][u][2*odd]     = bf16x2_of(p0, p1);
                    pa[mt][u][2*odd + 1] = bf16x2_of(p2, p3);
                }
            // ---- O += P V ----
            #pragma unroll
            for (int u = 0; u < 2; u++)
                #pragma unroll
                for (int db = 0; db < 4; db++) {
                    uint32_t b0 = *(const uint32_t*)&Vsm[8*db + g][c32 + 16*u + 2*t];
                    uint32_t b1 = *(const uint32_t*)&Vsm[8*db + g][c32 + 16*u + 8 + 2*t];
                    mma_bf16(o[0][db], pa[0][u], b0, b1);
                    mma_bf16(o[1][db], pa[1][u], b0, b1);
                }
        }
    }

    // reduce l over the t-quad, normalize, store ctx
    #pragma unroll
    for (int mt = 0; mt < 2; mt++)
        #pragma unroll
        for (int r = 0; r < 2; r++) {
            float v = lsum[mt][r];
            v += __shfl_xor_sync(0xffffffffu, v, 1);
            v += __shfl_xor_sync(0xffffffffu, v, 2);
            lsum[mt][r] = 1.f / v;
        }
    int b = bh >> 2;
    #pragma unroll
    for (int mt = 0; mt < 2; mt++) {
        int row = q0 + mt*16 + g;
        #pragma unroll
        for (int db = 0; db < 4; db++) {
            int dim = h*DK + 8*db + 2*t;
            float2 lo = make_float2(o[mt][db][0]*lsum[mt][0], o[mt][db][1]*lsum[mt][0]);
            float2 hi = make_float2(o[mt][db][2]*lsum[mt][1], o[mt][db][3]*lsum[mt][1]);
            *(float2*)(g_ctx + ((size_t)b*HW + row)*HD + dim)     = lo;
            *(float2*)(g_ctx + ((size_t)b*HW + row + 8)*HD + dim) = hi;
        }
    }
}

// ---------------- launch 4: output projection + residual, f32x2 packed ----------------
__global__ void k_out(const float* __restrict__ x,
                      const float* __restrict__ fco_w,
                      const float* __restrict__ fco_b,
                      float* __restrict__ out)
{
    __shared__ float cs[16*128];
    __shared__ float ws2[64*130];
    int b   = blockIdx.y;
    int p0  = blockIdx.x * 16;
    int tid = threadIdx.x;

    for (int e = tid; e < 8192; e += 256) {
        int ch = e >> 7, k = e & 127;
        ws2[ch*130+k] = fco_w[e];
    }
    const float* ctx = g_ctx + ((size_t)b*HW + p0)*HD;
    for (int e = tid; e < 2048; e += 256) cs[e] = ctx[e];
    __syncthreads();

    int ch = tid & 63;
    int pg = tid >> 6;
    ull acc2[4];
    #pragma unroll
    for (int pi = 0; pi < 4; pi++) acc2[pi] = 0ull;
    const ull* wr = (const ull*)(ws2 + ch*130);
    #pragma unroll 4
    for (int kp = 0; kp < 64; kp++) {
        ull w2 = wr[kp];
        #pragma unroll
        for (int pi = 0; pi < 4; pi++) {
            ull c2 = *(const ull*)(cs + (pg*4+pi)*128 + 2*kp);
            fma2(acc2[pi], w2, c2, acc2[pi]);
        }
    }
    float bias = fco_b[ch];
    #pragma unroll
    for (int pi = 0; pi < 4; pi++) {
        float a0, a1; unpack2(a0, a1, acc2[pi]);
        int pos = pg*4 + pi;
        size_t oi = (size_t)b*(C*HW) + (size_t)(p0+pos)*64 + ch;
        out[oi] = (a0 + a1) + bias + x[oi];
    }
}

// ---------------- launcher (5 launches; k_attn is launch idx 3) ----------------
extern "C" void kernel_launch(void* const* d_in, const int* in_sizes, int n_in,
                              void* d_out, int out_size)
{
    (void)n_in; (void)out_size; (void)in_sizes;
    const float* x      = (const float*)d_in[0];
    const float* wk     = (const float*)d_in[1];
    const float* wv     = (const float*)d_in[2];
    const float* fcq_w  = (const float*)d_in[3];
    const float* fcq_b  = (const float*)d_in[4];
    const float* fck_w  = (const float*)d_in[5];
    const float* fck_b  = (const float*)d_in[6];
    const float* fcv_w  = (const float*)d_in[7];
    const float* fcv_b  = (const float*)d_in[8];
    const float* fco_w  = (const float*)d_in[9];
    const float* fco_b  = (const float*)d_in[10];
    const float* Bmat   = (const float*)d_in[11];
    float* out = (float*)d_out;

    k_part<<<512, 256>>>(x);
    k_stats_weff<<<257, 512>>>(fck_w, wk, fcv_w, wv);
    k_qkv<<<dim3(256+64, BATCH), 128>>>(x, fcq_w, fcq_b, fck_b, fcv_b);
    k_attn<<<dim3(HW/128, BATCH*HEADS), 128>>>(Bmat);
    k_out<<<dim3(HW/16, BATCH), 256>>>(x, fco_w, fco_b, out);
}